// round 15
// baseline (speedup 1.0000x reference)
#include <cuda_runtime.h>
#include <stdint.h>
#include <math.h>

#define BATCH 128
#define SEQ   256
#define NC    16
#define HID   256
#define G4    1024              // 4*HID
#define NV    (BATCH*SEQ)       // 32768

// -------- scratch (static device arrays; no runtime alloc) ------------------
__device__ float g_x   [NV * HID];          // visit embeddings (33.5 MB)
__device__ float g_xp  [(size_t)NV * G4];   // input projections (134 MB)
__device__ float g_Ut  [HID * G4];          // Uall^T, k-major [256][1024]
__device__ float g_Wcat[HID * 1280];        // [k][g]: g<1024 Wall^T, g>=1024 Wd^T

// -------- helpers ------------------------------------------------------------
__device__ __forceinline__ float sigmoidf_(float x) { return 1.0f / (1.0f + expf(-x)); }

typedef unsigned long long ull_t;
// packed fp32x2 (Blackwell FFMA2 — PTX-only path, bit-exact fp32 per lane)
__device__ __forceinline__ ull_t pack2(float lo, float hi) {
    ull_t r; asm("mov.b64 %0, {%1, %2};" : "=l"(r) : "f"(lo), "f"(hi)); return r;
}
__device__ __forceinline__ ull_t packdup(float w) {
    ull_t r; asm("mov.b64 %0, {%1, %1};" : "=l"(r) : "f"(w)); return r;
}
__device__ __forceinline__ void ffma2(ull_t& d, ull_t a, ull_t b) {
    asm("fma.rn.f32x2 %0, %1, %2, %0;" : "+l"(d) : "l"(a), "l"(b));
}
__device__ __forceinline__ void addx2(ull_t& d, ull_t a) {
    asm("add.rn.f32x2 %0, %0, %1;" : "+l"(d) : "l"(a));
}
__device__ __forceinline__ void unpack2(float& lo, float& hi, ull_t v) {
    asm("mov.b64 {%0, %1}, %2;" : "=f"(lo), "=f"(hi) : "l"(v));
}
__device__ __forceinline__ void lds_v2u64(ull_t& a, ull_t& b, uint32_t addr) {
    asm volatile("ld.shared.v2.u64 {%0, %1}, [%2];" : "=l"(a), "=l"(b) : "r"(addr));
}
__device__ __forceinline__ void st_cluster_v4(uint32_t addr, float a, float b,
                                              float c, float d) {
    asm volatile("st.shared::cluster.v4.f32 [%0], {%1, %2, %3, %4};"
                 :: "r"(addr), "f"(a), "f"(b), "f"(c), "f"(d) : "memory");
}

// -------- K0: build transposed weight layouts --------------------------------
__global__ void k_transpose(const float* __restrict__ Wall,
                            const float* __restrict__ Uall,
                            const float* __restrict__ Wd) {
    int idx = blockIdx.x * blockDim.x + threadIdx.x;   // up to 327680
    if (idx < HID * G4) {
        int k = idx >> 10;          // 0..255
        int g = idx & 1023;         // 0..1023
        g_Ut[idx] = Uall[g * HID + k];
    }
    if (idx < HID * 1280) {
        int k = idx / 1280;
        int g = idx % 1280;
        g_Wcat[idx] = (g < 1024) ? Wall[g * HID + k] : Wd[(g - 1024) * HID + k];
    }
}

// -------- K1: embedding gather  x[v][j] = sum_nc emb[code][j]*mask -----------
__global__ void k_gather(const int*   __restrict__ codes,
                         const float* __restrict__ mask,
                         const float* __restrict__ emb) {
    int v = blockIdx.x;       // 0..NV-1
    int j = threadIdx.x;      // 0..255
    __shared__ int   sc[NC];
    __shared__ float sm[NC];
    if (j < NC) {
        sc[j] = codes[v * NC + j];
        sm[j] = mask [v * NC + j];
    }
    __syncthreads();
    float acc = 0.0f;
#pragma unroll
    for (int i = 0; i < NC; i++) {
        acc = fmaf(emb[sc[i] * HID + j], sm[i], acc);
    }
    g_x[v * HID + j] = acc;
}

// -------- K2: xp = x @ Uall^T + Uall_b  (fp32x2 packed GEMM) -----------------
// 64x64 tile, BK=32, 128 threads, 4 rows x 8 cols per thread via FFMA2.
#define BM 64
#define BN 64
#define BK 32
__global__ void __launch_bounds__(128)
k_xp(const float* __restrict__ bias) {
    __shared__ float As[BK][BM + 4];   // k-major A (transposed on load)
    __shared__ float Bs[BK][BN];

    int bn = blockIdx.x;   // 0..15   N tiles
    int bm = blockIdx.y;   // 0..511  M tiles
    int tid = threadIdx.x; // 0..127
    int tr = tid >> 3;     // 0..15 -> rows tr*4..tr*4+3
    int tc = tid & 7;      // 0..7  -> cols tc*8..tc*8+7

    const float* A  = g_x  + (size_t)bm * BM * HID;
    const float* Bt = g_Ut + bn * BN;

    ull_t acc[4][4];       // [row][colpair]
#pragma unroll
    for (int i = 0; i < 4; i++)
#pragma unroll
        for (int p = 0; p < 4; p++) acc[i][p] = pack2(0.0f, 0.0f);

    for (int k0 = 0; k0 < HID; k0 += BK) {
#pragma unroll
        for (int f = tid; f < BM * BK / 4; f += 128) {
            int r  = f >> 3;     // row 0..63
            int c4 = f & 7;      // k-group 0..7
            float4 v = *(const float4*)(A + r * HID + k0 + c4 * 4);
            As[c4 * 4 + 0][r] = v.x;
            As[c4 * 4 + 1][r] = v.y;
            As[c4 * 4 + 2][r] = v.z;
            As[c4 * 4 + 3][r] = v.w;
        }
#pragma unroll
        for (int f = tid; f < BK * BN / 4; f += 128) {
            int r  = f >> 4;     // k row 0..31
            int c4 = f & 15;     // float4 col 0..15
            *(float4*)&Bs[r][c4 * 4] = *(const float4*)(Bt + (size_t)(k0 + r) * G4 + c4 * 4);
        }
        __syncthreads();

#pragma unroll
        for (int kk = 0; kk < BK; kk++) {
            float4 a   = *(const float4*)&As[kk][tr * 4];
            float4 blo = *(const float4*)&Bs[kk][tc * 8];
            float4 bhi = *(const float4*)&Bs[kk][tc * 8 + 4];
            ull_t bp0 = pack2(blo.x, blo.y);
            ull_t bp1 = pack2(blo.z, blo.w);
            ull_t bp2 = pack2(bhi.x, bhi.y);
            ull_t bp3 = pack2(bhi.z, bhi.w);
            ull_t aa0 = packdup(a.x);
            ull_t aa1 = packdup(a.y);
            ull_t aa2 = packdup(a.z);
            ull_t aa3 = packdup(a.w);
            ffma2(acc[0][0], aa0, bp0); ffma2(acc[0][1], aa0, bp1);
            ffma2(acc[0][2], aa0, bp2); ffma2(acc[0][3], aa0, bp3);
            ffma2(acc[1][0], aa1, bp0); ffma2(acc[1][1], aa1, bp1);
            ffma2(acc[1][2], aa1, bp2); ffma2(acc[1][3], aa1, bp3);
            ffma2(acc[2][0], aa2, bp0); ffma2(acc[2][1], aa2, bp1);
            ffma2(acc[2][2], aa2, bp2); ffma2(acc[2][3], aa2, bp3);
            ffma2(acc[3][0], aa3, bp0); ffma2(acc[3][1], aa3, bp1);
            ffma2(acc[3][2], aa3, bp2); ffma2(acc[3][3], aa3, bp3);
        }
        __syncthreads();
    }

    float4 blo = *(const float4*)(bias + bn * BN + tc * 8);
    float4 bhi = *(const float4*)(bias + bn * BN + tc * 8 + 4);
    float* C = g_xp + (size_t)(bm * BM) * G4 + bn * BN;
#pragma unroll
    for (int i = 0; i < 4; i++) {
        float c0, c1, c2, c3, c4, c5, c6, c7;
        unpack2(c0, c1, acc[i][0]);
        unpack2(c2, c3, acc[i][1]);
        unpack2(c4, c5, acc[i][2]);
        unpack2(c6, c7, acc[i][3]);
        float* Cr = C + (size_t)(tr * 4 + i) * G4 + tc * 8;
        *(float4*)(Cr)     = make_float4(c0 + blo.x, c1 + blo.y, c2 + blo.z, c3 + blo.w);
        *(float4*)(Cr + 4) = make_float4(c4 + bhi.x, c5 + bhi.y, c6 + bhi.z, c7 + bhi.w);
    }
}

// -------- K3: recurrent scan — weight-stationary, k-split warps, FFMA2 -------
// 16 clusters x 8 CTAs (=128 SMs), 128 threads/CTA.
//   cluster c -> batches [c*8, c*8+8);  CTA rank r -> channels J=[r*32, r*32+32)
// k-loop role:  warp kw = tid>>5 owns k-slice [kw*64, kw*64+64), lane j=tid&31,
//               ALL 8 batches, accumulators packed f32x2 over batch pairs.
// epilogue role: thread = (j=tid&31, bp=tid>>5) -> batches {2bp, 2bp+1}.
// State layout [parity][bp][k][4] = {h_b0,h_b1,c_b0,c_b1}: one broadcast
// ld.shared.v2.u64 per (k,bp) yields both packed operands; producer pushes one
// st.shared::cluster.v4 per peer. Cross-warp reduction via smem staging.
//
// smem: sW  [256][160]                163840 B
//       sSt [2][4][256][4]             32768 B
//       sT  [8][256]                    8192 B
//       sRed[5][4][4][32] (ull)        20480 B     total 225280 <= 227KB
#define KREC_SMEM (256*160*4 + 2*4*256*4*4 + 8*256*4 + 5*4*4*32*8)

__global__ void __cluster_dims__(8, 1, 1) __launch_bounds__(128, 1)
k_rec(const float* __restrict__ times,
      const float* __restrict__ Wall_b,
      const float* __restrict__ Wd_b,
      float* __restrict__ out) {
    extern __shared__ float smem[];
    float* sW  = smem;                            // [256][160]
    float* sSt = smem + 256 * 160;                // [2][4][256][4]
    float* sT  = sSt + 2 * 4 * 256 * 4;           // [8][256]
    ull_t* sRed = (ull_t*)(sT + 8 * 256);         // [5][4 q][4 warp][32 j]

    const int tid  = threadIdx.x;
    const int rank = blockIdx.x & 7;
    const int clu  = blockIdx.x >> 3;
    const int j    = tid & 31;       // lane: channel within slice (both roles)
    const int kw   = tid >> 5;       // k-loop role: warp's k-slice
    const int bp   = tid >> 5;       // epilogue role: batch pair
    const int b0   = 2 * bp, b1 = 2 * bp + 1;
    const int J    = rank * 32 + j;  // global channel
    const int gb0  = clu * 8 + b0;   // global batch ids (epilogue role)
    const int gb1  = clu * 8 + b1;

    // ---- load weight slice into smem (float4) ----
    for (int f = tid; f < 256 * 40; f += 128) {
        int k    = f / 40;
        int c4   = f % 40;
        int gate = c4 >> 3;
        int jj4  = c4 & 7;
        float4 v = *(const float4*)(g_Wcat + (size_t)k * 1280 + gate * 256 + rank * 32 + jj4 * 4);
        *(float4*)(sW + k * 160 + gate * 32 + jj4 * 4) = v;
    }
    // ---- zero state (both parities) ----
    for (int f = tid; f < 2 * 4 * 256 * 4; f += 128) sSt[f] = 0.0f;
    // ---- precompute time decay for this cluster's 8 batches ----
    for (int f = tid; f < 8 * 256; f += 128) {
        int b = f >> 8, s = f & 255;
        sT[f] = 1.0f / logf(times[(size_t)(clu * 8 + b) * SEQ + s] + 2.7183f);
    }

    // ---- shared-window addresses ----
    uint32_t stBase, wBase;
    asm("{ .reg .u64 t; cvta.to.shared.u64 t, %1; cvt.u32.u64 %0, t; }"
        : "=r"(stBase) : "l"(sSt));
    asm("{ .reg .u64 t; cvta.to.shared.u64 t, %1; cvt.u32.u64 %0, t; }"
        : "=r"(wBase) : "l"(sW));
    uint32_t peer[8];
#pragma unroll
    for (int r2 = 0; r2 < 8; r2++)
        asm("mapa.shared::cluster.u32 %0, %1, %2;"
            : "=r"(peer[r2]) : "r"(stBase), "r"(r2));

    // ---- per-thread biases (epilogue role) ----
    const float bias_f  = Wall_b[0   + J];
    const float bias_i  = Wall_b[256 + J];
    const float bias_o  = Wall_b[512 + J];
    const float bias_ct = Wall_b[768 + J];
    const float bias_cs = Wd_b[J];

    // all CTAs' smem init visible cluster-wide (arrive=release, wait=acquire)
    asm volatile("barrier.cluster.arrive.aligned;" ::: "memory");
    asm volatile("barrier.cluster.wait.aligned;"   ::: "memory");

    int p = 0;
    for (int s = 0; s < SEQ; s++) {
        // ---- prefetch xp for THIS step (epilogue role); LDGs issue here,
        //      values consumed after the k-loop => latency hidden
        const float* x0 = g_xp + ((size_t)gb0 * SEQ + s) * G4;
        const float* x1 = g_xp + ((size_t)gb1 * SEQ + s) * G4;
        float pf00 = x0[0 + J],   pf10 = x0[256 + J],
              pf20 = x0[512 + J], pf30 = x0[768 + J];
        float pf01 = x1[0 + J],   pf11 = x1[256 + J],
              pf21 = x1[512 + J], pf31 = x1[768 + J];

        // ---- k-loop (role: kw, j): partial dot products, packed over pairs
        ull_t acc[5][4];
#pragma unroll
        for (int g = 0; g < 5; g++)
#pragma unroll
            for (int q = 0; q < 4; q++) acc[g][q] = pack2(0.0f, 0.0f);

        uint32_t stA = stBase + (uint32_t)p * 16384u + (uint32_t)(kw * 64) * 16u;
        uint32_t wA  = wBase + (uint32_t)(kw * 64) * 640u + (uint32_t)j * 4u;

#pragma unroll 2
        for (int it = 0; it < 64; it++) {
            ull_t hp0, cp0, hp1, cp1, hp2, cp2, hp3, cp3;
            lds_v2u64(hp0, cp0, stA);             // bp0  {h_b0,h_b1},{c_b0,c_b1}
            lds_v2u64(hp1, cp1, stA + 4096u);     // bp1
            lds_v2u64(hp2, cp2, stA + 8192u);     // bp2
            lds_v2u64(hp3, cp3, stA + 12288u);    // bp3
            float v0, v1, v2, v3, v4;
            asm volatile("ld.shared.f32 %0, [%1];"        : "=f"(v0) : "r"(wA));
            asm volatile("ld.shared.f32 %0, [%1+128];"    : "=f"(v1) : "r"(wA));
            asm volatile("ld.shared.f32 %0, [%1+256];"    : "=f"(v2) : "r"(wA));
            asm volatile("ld.shared.f32 %0, [%1+384];"    : "=f"(v3) : "r"(wA));
            asm volatile("ld.shared.f32 %0, [%1+512];"    : "=f"(v4) : "r"(wA));
            ull_t wf = packdup(v0), wi = packdup(v1), wo = packdup(v2),
                  wc = packdup(v3), wd = packdup(v4);
            ffma2(acc[0][0], wf, hp0); ffma2(acc[0][1], wf, hp1);
            ffma2(acc[0][2], wf, hp2); ffma2(acc[0][3], wf, hp3);
            ffma2(acc[1][0], wi, hp0); ffma2(acc[1][1], wi, hp1);
            ffma2(acc[1][2], wi, hp2); ffma2(acc[1][3], wi, hp3);
            ffma2(acc[2][0], wo, hp0); ffma2(acc[2][1], wo, hp1);
            ffma2(acc[2][2], wo, hp2); ffma2(acc[2][3], wo, hp3);
            ffma2(acc[3][0], wc, hp0); ffma2(acc[3][1], wc, hp1);
            ffma2(acc[3][2], wc, hp2); ffma2(acc[3][3], wc, hp3);
            ffma2(acc[4][0], wd, cp0); ffma2(acc[4][1], wd, cp1);
            ffma2(acc[4][2], wd, cp2); ffma2(acc[4][3], wd, cp3);
            stA += 16u;
            wA  += 640u;
        }

        // ---- stage partials: sRed[g][q][kw][j]  (conflict-free) ----
#pragma unroll
        for (int g = 0; g < 5; g++)
#pragma unroll
            for (int q = 0; q < 4; q++)
                sRed[((g * 4 + q) * 4 + kw) * 32 + j] = acc[g][q];
        __syncthreads();

        // ---- reduce across 4 warps (epilogue role: j, bp) ----
        ull_t sum[5];
#pragma unroll
        for (int g = 0; g < 5; g++) {
            const ull_t* rp = sRed + ((g * 4 + bp) * 4) * 32 + j;
            ull_t t0 = rp[0], t1 = rp[32], t2 = rp[64], t3 = rp[96];
            addx2(t0, t1); addx2(t2, t3); addx2(t0, t2);
            sum[g] = t0;
        }

        float aF0, aF1, aI0, aI1, aO0, aO1, aC0, aC1, aS0, aS1;
        unpack2(aF0, aF1, sum[0]);
        unpack2(aI0, aI1, sum[1]);
        unpack2(aO0, aO1, sum[2]);
        unpack2(aC0, aC1, sum[3]);
        unpack2(aS0, aS1, sum[4]);
        aF0 += bias_f  + pf00;  aF1 += bias_f  + pf01;
        aI0 += bias_i  + pf10;  aI1 += bias_i  + pf11;
        aO0 += bias_o  + pf20;  aO1 += bias_o  + pf21;
        aC0 += bias_ct + pf30;  aC1 += bias_ct + pf31;
        aS0 += bias_cs;         aS1 += bias_cs;

        // old c for own channels, parity p  (layout {h_b0,h_b1,c_b0,c_b1})
        const float* stOwn = sSt + ((p * 4 + bp) * 256 + J) * 4;
        float cold0 = stOwn[2];
        float cold1 = stOwn[3];

        float hn0, cn0, hn1, cn1;
        {
            float tsv = sT[b0 * 256 + s];
            float fg = sigmoidf_(aF0), ig = sigmoidf_(aI0);
            float og = sigmoidf_(aO0), ctg = sigmoidf_(aC0);
            float cs1 = tanhf(aS0);
            float cadj = (cold0 - cs1) + cs1 * tsv;
            cn0 = fg * cadj + ig * ctg;
            hn0 = og * tanhf(cn0);
        }
        {
            float tsv = sT[b1 * 256 + s];
            float fg = sigmoidf_(aF1), ig = sigmoidf_(aI1);
            float og = sigmoidf_(aO1), ctg = sigmoidf_(aC1);
            float cs1 = tanhf(aS1);
            float cadj = (cold1 - cs1) + cs1 * tsv;
            cn1 = fg * cadj + ig * ctg;
            hn1 = og * tanhf(cn1);
        }

        // write-through: out is written once and never re-read by the GPU
        __stwt(&out[((size_t)gb0 * SEQ + s) * HID + J], hn0);
        __stwt(&out[((size_t)gb1 * SEQ + s) * HID + J], hn1);

        // ---- broadcast {h_b0,h_b1,c_b0,c_b1} to all 8 CTAs (parity np) ----
        const int np = 1 - p;
        const uint32_t off = (uint32_t)(((np * 4 + bp) * 256 + J) * 4) * 4u;
#pragma unroll
        for (int r2 = 0; r2 < 8; r2++)
            st_cluster_v4(peer[r2] + off, hn0, hn1, cn0, cn1);

        // release our DSMEM writes / acquire peers' — one barrier per step
        asm volatile("barrier.cluster.arrive.aligned;" ::: "memory");
        asm volatile("barrier.cluster.wait.aligned;"   ::: "memory");
        p = np;
    }
}

// -------- launcher ------------------------------------------------------------
extern "C" void kernel_launch(void* const* d_in, const int* in_sizes, int n_in,
                              void* d_out, int out_size) {
    const int*   codes  = (const int*)  d_in[0];
    const float* mask   = (const float*)d_in[1];
    const float* times  = (const float*)d_in[2];
    const float* emb    = (const float*)d_in[3];
    const float* Wall_w = (const float*)d_in[4];
    const float* Wall_b = (const float*)d_in[5];
    const float* Uall_w = (const float*)d_in[6];
    const float* Uall_b = (const float*)d_in[7];
    const float* Wd_w   = (const float*)d_in[8];
    const float* Wd_b   = (const float*)d_in[9];
    float* out = (float*)d_out;

    cudaFuncSetAttribute(k_rec, cudaFuncAttributeMaxDynamicSharedMemorySize,
                         KREC_SMEM);

    k_transpose<<<1280, 256>>>(Wall_w, Uall_w, Wd_w);
    k_gather<<<NV, 256>>>(codes, mask, emb);
    dim3 g2(G4 / BN, NV / BM);   // (16, 512)
    k_xp<<<g2, 128>>>(Uall_b);
    k_rec<<<128, 128, KREC_SMEM>>>(times, Wall_b, Wd_b, out);
}